// round 1
// baseline (speedup 1.0000x reference)
#include <cuda_runtime.h>
#include <cuda_bf16.h>

// Chebyshev (L-inf) pairwise distance: out[i,j] = max_d |A[i,d] - B[j,d]|
// A: [N, 32] fp32, B: [M, 32] fp32, out: [N, M] fp32. N = M = 4096.
//
// GEMM-style tiling: 128x128 output tile per CTA, 256 threads, 8x8 register
// blocking. SMEM tiles are stored d-major (As[d][row]) so each d-step needs
// only 4 LDS.128 per thread against 128 math instructions.

constexpr int D    = 32;
constexpr int TILE = 128;

__global__ __launch_bounds__(256, 2)
void cheby_kernel(const float* __restrict__ A, const float* __restrict__ B,
                  float* __restrict__ out, int M) {
    __shared__ float As[D][TILE];
    __shared__ float Bs[D][TILE];

    const int tid = threadIdx.x;
    const int bi  = blockIdx.y * TILE;
    const int bj  = blockIdx.x * TILE;

    // Load A-tile and B-tile (TILE*D = 4096 floats each) as float4, transpose
    // into d-major smem. 256 threads x 4 float4 per tile.
    #pragma unroll
    for (int k = 0; k < 4; k++) {
        int idx = tid + k * 256;        // float4 index 0..1023
        int row = idx >> 3;             // 8 float4 per 32-wide row
        int dg  = (idx & 7) << 2;
        float4 va = *reinterpret_cast<const float4*>(A + (size_t)(bi + row) * D + dg);
        As[dg + 0][row] = va.x; As[dg + 1][row] = va.y;
        As[dg + 2][row] = va.z; As[dg + 3][row] = va.w;
        float4 vb = *reinterpret_cast<const float4*>(B + (size_t)(bj + row) * D + dg);
        Bs[dg + 0][row] = vb.x; Bs[dg + 1][row] = vb.y;
        Bs[dg + 2][row] = vb.z; Bs[dg + 3][row] = vb.w;
    }
    __syncthreads();

    const int tx = tid & 15;
    const int ty = tid >> 4;
    const int ri = ty * 8;
    const int rj = tx * 8;

    float acc[8][8];
    #pragma unroll
    for (int i = 0; i < 8; i++)
        #pragma unroll
        for (int j = 0; j < 8; j++)
            acc[i][j] = 0.0f;          // |diff| >= 0, so 0 is a safe identity

    #pragma unroll 4
    for (int d = 0; d < D; d++) {
        float a[8], b[8];
        *reinterpret_cast<float4*>(a + 0) = *reinterpret_cast<const float4*>(&As[d][ri + 0]);
        *reinterpret_cast<float4*>(a + 4) = *reinterpret_cast<const float4*>(&As[d][ri + 4]);
        *reinterpret_cast<float4*>(b + 0) = *reinterpret_cast<const float4*>(&Bs[d][rj + 0]);
        *reinterpret_cast<float4*>(b + 4) = *reinterpret_cast<const float4*>(&Bs[d][rj + 4]);
        #pragma unroll
        for (int i = 0; i < 8; i++)
            #pragma unroll
            for (int j = 0; j < 8; j++)
                acc[i][j] = fmaxf(acc[i][j], fabsf(a[i] - b[j]));
    }

    #pragma unroll
    for (int i = 0; i < 8; i++) {
        float* p = out + (size_t)(bi + ri + i) * M + (bj + rj);
        float4 v0 = make_float4(acc[i][0], acc[i][1], acc[i][2], acc[i][3]);
        float4 v1 = make_float4(acc[i][4], acc[i][5], acc[i][6], acc[i][7]);
        *reinterpret_cast<float4*>(p + 0) = v0;
        *reinterpret_cast<float4*>(p + 4) = v1;
    }
}

extern "C" void kernel_launch(void* const* d_in, const int* in_sizes, int n_in,
                              void* d_out, int out_size) {
    const float* A = (const float*)d_in[0];
    const float* B = (const float*)d_in[1];
    float* out = (float*)d_out;
    int N = in_sizes[0] / D;   // 4096
    int M = in_sizes[1] / D;   // 4096
    dim3 grid(M / TILE, N / TILE);
    cheby_kernel<<<grid, 256>>>(A, B, out, M);
}